// round 15
// baseline (speedup 1.0000x reference)
#include <cuda_runtime.h>
#include <cuda_fp16.h>

// Problem geometry (fixed by the dataset)
#define W     1920
#define H     1080
#define NPL   6            // B*C planes
#define HWSZ  (H*W)
#define NTOT  (NPL*HWSZ)   // 12,441,600
#define KS    51
#define RAD   25
#define W2    (W/2)        // 960 pair-columns

typedef unsigned long long u64;   // packed f32x2

// Scratch (allocation-free rule: __device__ globals)
__device__ __half        g_tmpAh[NTOT];   // H-blurred img, fp16
__device__ __half        g_delta[NTOT];   // clip(img+0.5res)-img, fp16
__device__ unsigned char g_mask[NTOT];    // threshold mask, exact {0,1}
__device__ __half        g_tmpCh[NTOT];   // H-blurred mask, fp16
__device__ u64           g_kpair[KS];
__constant__ u64         c_kpair[KS];     // (k,k) pairs -> uniform const port

// ---- packed f32x2 helpers (sm_103a) ----
__device__ __forceinline__ u64 pack2(float x, float y) {
    u64 r; asm("mov.b64 %0, {%1, %2};" : "=l"(r) : "f"(x), "f"(y)); return r;
}
__device__ __forceinline__ void unpack2(u64 v, float& x, float& y) {
    asm("mov.b64 {%0, %1}, %2;" : "=f"(x), "=f"(y) : "l"(v));
}
__device__ __forceinline__ u64 fma2(u64 a, u64 b, u64 c) {
    u64 d; asm("fma.rn.f32x2 %0, %1, %2, %3;" : "=l"(d) : "l"(a), "l"(b), "l"(c));
    return d;
}
__device__ __forceinline__ u64 h2_to_u64(__half2 h) {
    float2 f = __half22float2(h);
    return pack2(f.x, f.y);
}

// --- 1D kernel extraction: 2D kernel is outer product k1*k1^T with sum(k1)=1,
// so row-sums recover k1 exactly (up to fp32 rounding). Store (k,k) pairs. ---
__global__ void k1d_kernel(const float* __restrict__ k2d) {
    int i = threadIdx.x;
    if (i < KS) {
        float s = 0.f;
        #pragma unroll
        for (int j = 0; j < KS; j++) s += k2d[i * KS + j];
        g_kpair[i] = pack2(s, s);
    }
}

__device__ __forceinline__ int reflect_idx(int i, int n) {
    // jnp.pad mode='reflect' (mirror WITHOUT repeating the edge)
    if (i < 0)  i = -i;
    if (i >= n) i = 2 * n - 2 - i;
    return i;
}

// ====== Horizontal conv: row-pair f32x2, j-scatter mainloop =================
// Block = 8 warps; each warp owns ONE row-pair and a 160-wide x tile
// (32 lanes x 5 consecutive outputs). 1920 = 12*160 exact; planes are
// even-height so pairs never straddle planes. Data LDS.64 at u64-index
// 5*lane+j: conflict-free (gcd(5,32)=1). Weights from __constant__ with
// compile-time indices. j-scatter: 1 LDS + <=5 FFMA2 per window element,
// zero window bookkeeping.
#define HR     5
#define HTILE  (32 * HR)          // 160
#define HWARPS 8
#define HWIN   (HTILE + 2 * RAD)  // 210
#define HTAPS  (KS + HR - 1)      // 55

#define HCONV_CORE_AND_EPILOG                                                  \
    __syncwarp();                                                              \
    const int o = lane * HR;                                                   \
    u64 acc[HR];                                                               \
    _Pragma("unroll")                                                          \
    for (int r = 0; r < HR; r++) acc[r] = 0ull;                                \
    _Pragma("unroll")                                                          \
    for (int j = 0; j < HTAPS; j++) {                                          \
        u64 v = s2[wp][o + j];                                                 \
        _Pragma("unroll")                                                      \
        for (int r = 0; r < HR; r++)                                           \
            if (j - r >= 0 && j - r < KS)          /* compile-time */          \
                acc[r] = fma2(c_kpair[j - r], v, acc[r]);                      \
    }                                                                          \
    __half* o0 = out + (size_t)(2 * rp) * W + x0 + o;                          \
    __half* o1 = o0 + W;                                                       \
    _Pragma("unroll")                                                          \
    for (int r = 0; r < HR; r++) {                                             \
        float a, b; unpack2(acc[r], a, b);                                     \
        o0[r] = __float2half_rn(a); o1[r] = __float2half_rn(b);                \
    }

// Pass 2: fp32 img in -> fp16 h-blur out.
__global__ void __launch_bounds__(256, 4) hconv_img_kernel(const float* __restrict__ in,
                                                           __half* __restrict__ out) {
    __shared__ u64 s2[HWARPS][HWIN + 1];
    const int tid = threadIdx.x, lane = tid & 31, wp = tid >> 5;
    const int rp = blockIdx.y * HWARPS + wp;
    const int x0 = blockIdx.x * HTILE;

    const float* r0 = in + (size_t)(2 * rp) * W;
    const float* r1 = r0 + W;
    if (blockIdx.x >= 1 && blockIdx.x <= 10) {      // interior: no reflect
        const float* p0 = r0 + x0 - RAD;
        const float* p1 = r1 + x0 - RAD;
        #pragma unroll
        for (int ii = 0; ii < (HWIN + 31) / 32; ii++) {
            int i = lane + 32 * ii;
            if (ii < HWIN / 32 || i < HWIN)
                s2[wp][i] = pack2(p0[i], p1[i]);
        }
    } else {
        for (int i = lane; i < HWIN; i += 32) {
            int x = reflect_idx(x0 - RAD + i, W);
            s2[wp][i] = pack2(r0[x], r1[x]);
        }
    }
    HCONV_CORE_AND_EPILOG
}

// Pass 4: u8 mask in (exact 0/1) -> fp16 h-blur out.
__global__ void __launch_bounds__(256, 4) hconv_mask_kernel(const unsigned char* __restrict__ in,
                                                            __half* __restrict__ out) {
    __shared__ u64 s2[HWARPS][HWIN + 1];
    const int tid = threadIdx.x, lane = tid & 31, wp = tid >> 5;
    const int rp = blockIdx.y * HWARPS + wp;
    const int x0 = blockIdx.x * HTILE;

    const unsigned char* r0 = in + (size_t)(2 * rp) * W;
    const unsigned char* r1 = r0 + W;
    if (blockIdx.x >= 1 && blockIdx.x <= 10) {      // interior: no reflect
        const unsigned char* p0 = r0 + x0 - RAD;
        const unsigned char* p1 = r1 + x0 - RAD;
        #pragma unroll
        for (int ii = 0; ii < (HWIN + 31) / 32; ii++) {
            int i = lane + 32 * ii;
            if (ii < HWIN / 32 || i < HWIN)
                s2[wp][i] = pack2((float)p0[i], (float)p1[i]);
        }
    } else {
        for (int i = lane; i < HWIN; i += 32) {
            int x = reflect_idx(x0 - RAD + i, W);
            s2[wp][i] = pack2((float)r0[x], (float)r1[x]);
        }
    }
    HCONV_CORE_AND_EPILOG
}

// ====== Vertical conv: column-pair f32x2, j-scatter mainloop ================
// Block (32,12): 32 lanes = 32 pair-columns; each thread computes 8
// consecutive y outputs; block covers 96 rows (halo 146/96 = 1.52x).
// Input is fp16 (half2 per pair-column), converted to f32x2 at smem fill.
#define VR    8
#define VTY   12
#define VTILE (VR * VTY)          // 96 rows per block
#define VWIN  (VTILE + 2 * RAD)   // 146
#define VTAPS (KS + VR - 1)       // 58

__device__ __forceinline__ void vconv_fill(u64 (*st)[32], const __half2* in,
                                           int by, int y0, int tx, int ty,
                                           int c, size_t pb) {
    if (by >= 1 && by <= 9) {                       // interior: no reflect
        const __half2* p = in + pb + (size_t)(y0 - RAD) * W2 + c;
        #pragma unroll
        for (int ii = 0; ii < (VWIN + VTY - 1) / VTY; ii++) {
            int i = ty + VTY * ii;
            if (ii < VWIN / VTY || i < VWIN)
                st[i][tx] = h2_to_u64(p[(size_t)i * W2]);
        }
    } else {
        for (int i = ty; i < VWIN; i += VTY) {
            int y = reflect_idx(y0 - RAD + i, H);
            st[i][tx] = h2_to_u64(in[pb + (size_t)y * W2 + c]);
        }
    }
}

__device__ __forceinline__ void vconv_core(const u64 (*st)[32], int yb, int tx,
                                           u64 acc[VR]) {
    #pragma unroll
    for (int r = 0; r < VR; r++) acc[r] = 0ull;

    #pragma unroll
    for (int j = 0; j < VTAPS; j++) {
        u64 v = st[yb + j][tx];
        #pragma unroll
        for (int r = 0; r < VR; r++)
            if (j - r >= 0 && j - r < KS)           // compile-time
                acc[r] = fma2(c_kpair[j - r], v, acc[r]);
    }
}

// Pass 3: blur = Vconv(tmpAh); write delta = clip(img+0.5res)-img (fp16) and
// mask (u8, exact).
__global__ void __launch_bounds__(384, 3) vconv_res_kernel(const __half2* __restrict__ in,
                                                           const u64* __restrict__ img,
                                                           __half2* __restrict__ delta_out,
                                                           uchar2* __restrict__ mask_out) {
    __shared__ u64 st[VWIN][32];
    const int tx = threadIdx.x, ty = threadIdx.y;
    const int c  = blockIdx.x * 32 + tx;      // pair-column, < W2
    const int y0 = blockIdx.y * VTILE;
    const size_t pb = (size_t)blockIdx.z * (HWSZ / 2);

    vconv_fill(st, in, blockIdx.y, y0, tx, ty, c, pb);
    __syncthreads();

    u64 acc[VR];
    vconv_core(st, ty * VR, tx, acc);

    #pragma unroll
    for (int r = 0; r < VR; r++) {
        int y = y0 + ty * VR + r;
        if (y < H) {
            size_t idx = pb + (size_t)y * W2 + c;
            float bx, by, ix, iy;
            unpack2(acc[r], bx, by);
            unpack2(img[idx], ix, iy);
            float rx = ix - bx, ry = iy - by;
            float dx = fminf(fmaxf(fmaf(0.5f, rx, ix), 0.0f), 1.0f) - ix;
            float dy = fminf(fmaxf(fmaf(0.5f, ry, iy), 0.0f), 1.0f) - iy;
            delta_out[idx] = __floats2half2_rn(dx, dy);
            unsigned char mx = (fabsf(rx) * 255.0f > 10.0f) ? 1 : 0;
            unsigned char my = (fabsf(ry) * 255.0f > 10.0f) ? 1 : 0;
            mask_out[idx] = make_uchar2(mx, my);
        }
    }
}

// Pass 5: soft_mask = Vconv(tmpCh); out = img + soft*delta. Write-only out.
__global__ void __launch_bounds__(384, 3) vconv_final_kernel(const __half2* __restrict__ in,
                                                             const u64* __restrict__ img,
                                                             const __half2* __restrict__ delta,
                                                             u64* __restrict__ out) {
    __shared__ u64 st[VWIN][32];
    const int tx = threadIdx.x, ty = threadIdx.y;
    const int c  = blockIdx.x * 32 + tx;
    const int y0 = blockIdx.y * VTILE;
    const size_t pb = (size_t)blockIdx.z * (HWSZ / 2);

    vconv_fill(st, in, blockIdx.y, y0, tx, ty, c, pb);
    __syncthreads();

    u64 acc[VR];
    vconv_core(st, ty * VR, tx, acc);

    #pragma unroll
    for (int r = 0; r < VR; r++) {
        int y = y0 + ty * VR + r;
        if (y < H) {
            size_t idx = pb + (size_t)y * W2 + c;
            float sx, sy, ix, iy;
            unpack2(acc[r], sx, sy);
            unpack2(img[idx], ix, iy);
            float2 d = __half22float2(delta[idx]);
            float ox = fmaf(sx, d.x, ix);
            float oy = fmaf(sy, d.y, iy);
            out[idx] = pack2(ox, oy);
        }
    }
}

extern "C" void kernel_launch(void* const* d_in, const int* in_sizes, int n_in,
                              void* d_out, int out_size) {
    const float* img = (const float*)d_in[0];   // [2,3,1080,1920] fp32
    const float* k2d = (const float*)d_in[1];   // [51,51] fp32
    float* out = (float*)d_out;

    __half *tmpAh, *tmpCh, *delta;
    unsigned char* mask;
    u64* kpair;
    cudaGetSymbolAddress((void**)&tmpAh, g_tmpAh);
    cudaGetSymbolAddress((void**)&tmpCh, g_tmpCh);
    cudaGetSymbolAddress((void**)&delta, g_delta);
    cudaGetSymbolAddress((void**)&mask,  g_mask);
    cudaGetSymbolAddress((void**)&kpair, g_kpair);

    // 1) recover 1D kernel as (k,k) pairs, then stage into __constant__
    k1d_kernel<<<1, 64>>>(k2d);
    cudaMemcpyToSymbolAsync(c_kpair, kpair, KS * sizeof(u64), 0,
                            cudaMemcpyDeviceToDevice);

    dim3 hgrid(W / HTILE, (NPL * H / 2) / HWARPS);              // (12, 405)
    dim3 vgrid(W2 / 32, (H + VTILE - 1) / VTILE, NPL);          // (30, 12, 6)
    dim3 vblk(32, VTY);

    // 2) horizontal blur of img -> fp16
    hconv_img_kernel<<<hgrid, 256>>>(img, tmpAh);
    // 3) vertical blur + delta (fp16) + mask (u8)
    vconv_res_kernel<<<vgrid, vblk>>>((const __half2*)tmpAh, (const u64*)img,
                                      (__half2*)delta, (uchar2*)mask);
    // 4) horizontal blur of u8 mask -> fp16
    hconv_mask_kernel<<<hgrid, 256>>>(mask, tmpCh);
    // 5) vertical blur of mask + blend -> d_out (write-only)
    vconv_final_kernel<<<vgrid, vblk>>>((const __half2*)tmpCh, (const u64*)img,
                                        (const __half2*)delta, (u64*)out);
}

// round 16
// speedup vs baseline: 1.0608x; 1.0608x over previous
#include <cuda_runtime.h>
#include <cuda_fp16.h>

// Problem geometry (fixed by the dataset)
#define W     1920
#define H     1080
#define NPL   6            // B*C planes
#define HWSZ  (H*W)
#define NTOT  (NPL*HWSZ)   // 12,441,600
#define KS    51
#define RAD   25
#define W2    (W/2)        // 960 pair-columns

typedef unsigned long long u64;   // packed f32x2

// Scratch (allocation-free rule: __device__ globals)
__device__ __half        g_tmpAh[NTOT];   // H-blurred img, fp16
__device__ __half        g_delta[NTOT];   // clip(img+0.5res)-img, fp16
__device__ unsigned char g_mask[NTOT];    // threshold mask, exact {0,1}
__device__ __half        g_tmpCh[NTOT];   // H-blurred mask, fp16
__device__ u64           g_kpair[KS];
__constant__ u64         c_kpair[KS];     // (k,k) pairs -> uniform const port

// ---- packed f32x2 helpers (sm_103a) ----
__device__ __forceinline__ u64 pack2(float x, float y) {
    u64 r; asm("mov.b64 %0, {%1, %2};" : "=l"(r) : "f"(x), "f"(y)); return r;
}
__device__ __forceinline__ void unpack2(u64 v, float& x, float& y) {
    asm("mov.b64 {%0, %1}, %2;" : "=f"(x), "=f"(y) : "l"(v));
}
__device__ __forceinline__ u64 fma2(u64 a, u64 b, u64 c) {
    u64 d; asm("fma.rn.f32x2 %0, %1, %2, %3;" : "=l"(d) : "l"(a), "l"(b), "l"(c));
    return d;
}
__device__ __forceinline__ u64 h2_to_u64(__half2 h) {
    float2 f = __half22float2(h);
    return pack2(f.x, f.y);
}

// --- 1D kernel extraction: 2D kernel is outer product k1*k1^T with sum(k1)=1,
// so row-sums recover k1 exactly (up to fp32 rounding). Store (k,k) pairs. ---
__global__ void k1d_kernel(const float* __restrict__ k2d) {
    int i = threadIdx.x;
    if (i < KS) {
        float s = 0.f;
        #pragma unroll
        for (int j = 0; j < KS; j++) s += k2d[i * KS + j];
        g_kpair[i] = pack2(s, s);
    }
}

__device__ __forceinline__ int reflect_idx(int i, int n) {
    // jnp.pad mode='reflect' (mirror WITHOUT repeating the edge)
    if (i < 0)  i = -i;
    if (i >= n) i = 2 * n - 2 - i;
    return i;
}

// ====== Horizontal conv: row-pair f32x2, j-scatter, HR=15 ===================
// Block = 8 warps; each warp owns ONE row-pair and a 480-wide x tile
// (32 lanes x 15 consecutive outputs). 1920 = 4*480 exact; planes are
// even-height so pairs never straddle planes. Data LDS.64 at u64-index
// 15*lane+j: gcd(15,32)=1 -> conflict-free per half-warp. Weights from
// __constant__ at compile-time indices. Epilogue transposes through the
// warp-private smem row so global half-stores are unit-stride.
#define HR     15
#define HTILE  (32 * HR)          // 480
#define HWARPS 8
#define HWIN   (HTILE + 2 * RAD)  // 530
#define HTAPS  (KS + HR - 1)      // 65

#define HCONV_CORE_AND_EPILOG                                                  \
    __syncwarp();                                                              \
    const int o = lane * HR;                                                   \
    u64 acc[HR];                                                               \
    _Pragma("unroll")                                                          \
    for (int r = 0; r < HR; r++) acc[r] = 0ull;                                \
    _Pragma("unroll")                                                          \
    for (int j = 0; j < HTAPS; j++) {                                          \
        u64 v = s2[wp][o + j];                                                 \
        _Pragma("unroll")                                                      \
        for (int r = 0; r < HR; r++)                                           \
            if (j - r >= 0 && j - r < KS)          /* compile-time */          \
                acc[r] = fma2(c_kpair[j - r], v, acc[r]);                      \
    }                                                                          \
    __syncwarp();                                                              \
    _Pragma("unroll")                                                          \
    for (int r = 0; r < HR; r++) s2[wp][o + r] = acc[r];                       \
    __syncwarp();                                                              \
    __half* o0 = out + (size_t)(2 * rp) * W + x0;                              \
    __half* o1 = o0 + W;                                                       \
    _Pragma("unroll")                                                          \
    for (int j = 0; j < HR; j++) {                                             \
        float a, b; unpack2(s2[wp][lane + 32 * j], a, b);                      \
        o0[lane + 32 * j] = __float2half_rn(a);                                \
        o1[lane + 32 * j] = __float2half_rn(b);                                \
    }

// Pass 2: fp32 img in -> fp16 h-blur out.
__global__ void __launch_bounds__(256, 4) hconv_img_kernel(const float* __restrict__ in,
                                                           __half* __restrict__ out) {
    __shared__ u64 s2[HWARPS][HWIN + 1];
    const int tid = threadIdx.x, lane = tid & 31, wp = tid >> 5;
    const int rp = blockIdx.y * HWARPS + wp;
    const int x0 = blockIdx.x * HTILE;

    const float* r0 = in + (size_t)(2 * rp) * W;
    const float* r1 = r0 + W;
    if (blockIdx.x >= 1 && blockIdx.x <= 2) {       // interior: no reflect
        const float* p0 = r0 + x0 - RAD;
        const float* p1 = r1 + x0 - RAD;
        #pragma unroll
        for (int ii = 0; ii < (HWIN + 31) / 32; ii++) {
            int i = lane + 32 * ii;
            if (ii < HWIN / 32 || i < HWIN)
                s2[wp][i] = pack2(p0[i], p1[i]);
        }
    } else {
        for (int i = lane; i < HWIN; i += 32) {
            int x = reflect_idx(x0 - RAD + i, W);
            s2[wp][i] = pack2(r0[x], r1[x]);
        }
    }
    HCONV_CORE_AND_EPILOG
}

// Pass 4: u8 mask in (exact 0/1) -> fp16 h-blur out.
__global__ void __launch_bounds__(256, 4) hconv_mask_kernel(const unsigned char* __restrict__ in,
                                                            __half* __restrict__ out) {
    __shared__ u64 s2[HWARPS][HWIN + 1];
    const int tid = threadIdx.x, lane = tid & 31, wp = tid >> 5;
    const int rp = blockIdx.y * HWARPS + wp;
    const int x0 = blockIdx.x * HTILE;

    const unsigned char* r0 = in + (size_t)(2 * rp) * W;
    const unsigned char* r1 = r0 + W;
    if (blockIdx.x >= 1 && blockIdx.x <= 2) {       // interior: no reflect
        const unsigned char* p0 = r0 + x0 - RAD;
        const unsigned char* p1 = r1 + x0 - RAD;
        #pragma unroll
        for (int ii = 0; ii < (HWIN + 31) / 32; ii++) {
            int i = lane + 32 * ii;
            if (ii < HWIN / 32 || i < HWIN)
                s2[wp][i] = pack2((float)p0[i], (float)p1[i]);
        }
    } else {
        for (int i = lane; i < HWIN; i += 32) {
            int x = reflect_idx(x0 - RAD + i, W);
            s2[wp][i] = pack2((float)r0[x], (float)r1[x]);
        }
    }
    HCONV_CORE_AND_EPILOG
}

// ====== Vertical conv: column-pair f32x2, j-scatter, VR=16 ==================
// Block (32,6): 32 lanes = 32 pair-columns; each thread computes 16
// consecutive y outputs; block covers 96 rows (halo 146/96 = 1.52x).
// Input is fp16 (half2 per pair-column), converted to f32x2 at smem fill.
#define VR    16
#define VTY   6
#define VTILE (VR * VTY)          // 96 rows per block
#define VWIN  (VTILE + 2 * RAD)   // 146
#define VTAPS (KS + VR - 1)       // 66

__device__ __forceinline__ void vconv_fill(u64 (*st)[32], const __half2* in,
                                           int by, int y0, int tx, int ty,
                                           int c, size_t pb) {
    if (by >= 1 && by <= 9) {                       // interior: no reflect
        const __half2* p = in + pb + (size_t)(y0 - RAD) * W2 + c;
        #pragma unroll
        for (int ii = 0; ii < (VWIN + VTY - 1) / VTY; ii++) {
            int i = ty + VTY * ii;
            if (ii < VWIN / VTY || i < VWIN)
                st[i][tx] = h2_to_u64(p[(size_t)i * W2]);
        }
    } else {
        for (int i = ty; i < VWIN; i += VTY) {
            int y = reflect_idx(y0 - RAD + i, H);
            st[i][tx] = h2_to_u64(in[pb + (size_t)y * W2 + c]);
        }
    }
}

__device__ __forceinline__ void vconv_core(const u64 (*st)[32], int yb, int tx,
                                           u64 acc[VR]) {
    #pragma unroll
    for (int r = 0; r < VR; r++) acc[r] = 0ull;

    #pragma unroll
    for (int j = 0; j < VTAPS; j++) {
        u64 v = st[yb + j][tx];
        #pragma unroll
        for (int r = 0; r < VR; r++)
            if (j - r >= 0 && j - r < KS)           // compile-time
                acc[r] = fma2(c_kpair[j - r], v, acc[r]);
    }
}

// Pass 3: blur = Vconv(tmpAh); write delta = clip(img+0.5res)-img (fp16) and
// mask (u8, exact).
__global__ void __launch_bounds__(192, 5) vconv_res_kernel(const __half2* __restrict__ in,
                                                           const u64* __restrict__ img,
                                                           __half2* __restrict__ delta_out,
                                                           uchar2* __restrict__ mask_out) {
    __shared__ u64 st[VWIN][32];
    const int tx = threadIdx.x, ty = threadIdx.y;
    const int c  = blockIdx.x * 32 + tx;      // pair-column, < W2
    const int y0 = blockIdx.y * VTILE;
    const size_t pb = (size_t)blockIdx.z * (HWSZ / 2);

    vconv_fill(st, in, blockIdx.y, y0, tx, ty, c, pb);
    __syncthreads();

    u64 acc[VR];
    vconv_core(st, ty * VR, tx, acc);

    #pragma unroll
    for (int r = 0; r < VR; r++) {
        int y = y0 + ty * VR + r;
        if (y < H) {
            size_t idx = pb + (size_t)y * W2 + c;
            float bx, by, ix, iy;
            unpack2(acc[r], bx, by);
            unpack2(img[idx], ix, iy);
            float rx = ix - bx, ry = iy - by;
            float dx = fminf(fmaxf(fmaf(0.5f, rx, ix), 0.0f), 1.0f) - ix;
            float dy = fminf(fmaxf(fmaf(0.5f, ry, iy), 0.0f), 1.0f) - iy;
            delta_out[idx] = __floats2half2_rn(dx, dy);
            unsigned char mx = (fabsf(rx) * 255.0f > 10.0f) ? 1 : 0;
            unsigned char my = (fabsf(ry) * 255.0f > 10.0f) ? 1 : 0;
            mask_out[idx] = make_uchar2(mx, my);
        }
    }
}

// Pass 5: soft_mask = Vconv(tmpCh); out = img + soft*delta. Write-only out.
__global__ void __launch_bounds__(192, 5) vconv_final_kernel(const __half2* __restrict__ in,
                                                             const u64* __restrict__ img,
                                                             const __half2* __restrict__ delta,
                                                             u64* __restrict__ out) {
    __shared__ u64 st[VWIN][32];
    const int tx = threadIdx.x, ty = threadIdx.y;
    const int c  = blockIdx.x * 32 + tx;
    const int y0 = blockIdx.y * VTILE;
    const size_t pb = (size_t)blockIdx.z * (HWSZ / 2);

    vconv_fill(st, in, blockIdx.y, y0, tx, ty, c, pb);
    __syncthreads();

    u64 acc[VR];
    vconv_core(st, ty * VR, tx, acc);

    #pragma unroll
    for (int r = 0; r < VR; r++) {
        int y = y0 + ty * VR + r;
        if (y < H) {
            size_t idx = pb + (size_t)y * W2 + c;
            float sx, sy, ix, iy;
            unpack2(acc[r], sx, sy);
            unpack2(img[idx], ix, iy);
            float2 d = __half22float2(delta[idx]);
            float ox = fmaf(sx, d.x, ix);
            float oy = fmaf(sy, d.y, iy);
            out[idx] = pack2(ox, oy);
        }
    }
}

extern "C" void kernel_launch(void* const* d_in, const int* in_sizes, int n_in,
                              void* d_out, int out_size) {
    const float* img = (const float*)d_in[0];   // [2,3,1080,1920] fp32
    const float* k2d = (const float*)d_in[1];   // [51,51] fp32
    float* out = (float*)d_out;

    __half *tmpAh, *tmpCh, *delta;
    unsigned char* mask;
    u64* kpair;
    cudaGetSymbolAddress((void**)&tmpAh, g_tmpAh);
    cudaGetSymbolAddress((void**)&tmpCh, g_tmpCh);
    cudaGetSymbolAddress((void**)&delta, g_delta);
    cudaGetSymbolAddress((void**)&mask,  g_mask);
    cudaGetSymbolAddress((void**)&kpair, g_kpair);

    // 1) recover 1D kernel as (k,k) pairs, then stage into __constant__
    k1d_kernel<<<1, 64>>>(k2d);
    cudaMemcpyToSymbolAsync(c_kpair, kpair, KS * sizeof(u64), 0,
                            cudaMemcpyDeviceToDevice);

    dim3 hgrid(W / HTILE, (NPL * H / 2) / HWARPS);              // (4, 405)
    dim3 vgrid(W2 / 32, (H + VTILE - 1) / VTILE, NPL);          // (30, 12, 6)
    dim3 vblk(32, VTY);

    // 2) horizontal blur of img -> fp16
    hconv_img_kernel<<<hgrid, 256>>>(img, tmpAh);
    // 3) vertical blur + delta (fp16) + mask (u8)
    vconv_res_kernel<<<vgrid, vblk>>>((const __half2*)tmpAh, (const u64*)img,
                                      (__half2*)delta, (uchar2*)mask);
    // 4) horizontal blur of u8 mask -> fp16
    hconv_mask_kernel<<<hgrid, 256>>>(mask, tmpCh);
    // 5) vertical blur of mask + blend -> d_out (write-only)
    vconv_final_kernel<<<vgrid, vblk>>>((const __half2*)tmpCh, (const u64*)img,
                                        (const __half2*)delta, (u64*)out);
}